// round 1
// baseline (speedup 1.0000x reference)
#include <cuda_runtime.h>
#include <cstdint>
#include <cstdio>

#define T_STEPS 512
#define B_SZ 128
#define I_SZ 256
#define H_SZ 256
#define BH (B_SZ*H_SZ)

// ---------------- device scratch ----------------
__device__ float d_zx[4*B_SZ*I_SZ];                       // (4,B,I)
__device__ float d_zh[4*B_SZ*H_SZ];                       // (4,B,H)
__device__ float d_xpre[(size_t)T_STEPS*B_SZ*4*H_SZ];     // (T,B,4,H) 256MB
__device__ unsigned g_bar;

__global__ void reset_kernel() { g_bar = 0u; }

// ---------------- masks ----------------
__device__ __forceinline__ float concrete_mask(float u) {
    const float EPSC = 1e-7f;
    float logit_p = logf(0.25f + EPSC) - logf(0.75f + EPSC);
    float lu = logf(u + EPSC) - logf(1.0f - u + EPSC);
    float x = (logit_p + lu) / 0.1f;
    float s = 1.0f / (1.0f + expf(-x));
    return (1.0f - s) / 0.75f;
}

__global__ void mask_kernel(const float* __restrict__ ux, const float* __restrict__ uh) {
    int i = blockIdx.x * blockDim.x + threadIdx.x;
    if (i < 4*B_SZ*I_SZ) {
        d_zx[i] = concrete_mask(ux[i]);
        d_zh[i] = concrete_mask(uh[i]);
    }
}

// ---------------- x_pre GEMM ----------------
// x_pre[t,b,g,h] = sum_i input[t,b,i]*zx[g,b,i]*W[g,h,i] + Wb[g,h]
// M tile = 128 rows = exactly one t (b == local row). BN=64, BK=16. 256 thr, 8x4 tile.
#define XB_BM 128
#define XB_BN 64
#define XB_BK 16

__global__ __launch_bounds__(256) void xpre_kernel(
    const float* __restrict__ input, const float* __restrict__ W, const float* __restrict__ Wb)
{
    __shared__ float As[XB_BK][XB_BM+4];
    __shared__ float Bs[XB_BK][XB_BN+4];
    int g  = blockIdx.z;
    int t  = blockIdx.x;            // m0 = t*128
    int n0 = blockIdx.y * XB_BN;
    int tid = threadIdx.x;
    int tx = tid & 15, ty = tid >> 4;

    float acc[8][4];
    #pragma unroll
    for (int r = 0; r < 8; r++)
        #pragma unroll
        for (int c = 0; c < 4; c++) acc[r][c] = 0.f;

    const float* inpBase = input + (size_t)t * (B_SZ*I_SZ);
    const float* zxBase  = d_zx + g * (B_SZ*I_SZ);
    const float* wBase   = W + (size_t)g * (H_SZ*I_SZ) + (size_t)n0 * I_SZ;

    int lrow   = tid >> 2;          // 0..63
    int lchunk = (tid & 3) * 4;     // 0,4,8,12

    for (int kk0 = 0; kk0 < I_SZ; kk0 += XB_BK) {
        #pragma unroll
        for (int it = 0; it < 2; it++) {
            int row = lrow + it*64;
            float4 av = *(const float4*)(inpBase + row*I_SZ + kk0 + lchunk);
            float4 zv = *(const float4*)(zxBase  + row*I_SZ + kk0 + lchunk);
            As[lchunk+0][row] = av.x*zv.x;
            As[lchunk+1][row] = av.y*zv.y;
            As[lchunk+2][row] = av.z*zv.z;
            As[lchunk+3][row] = av.w*zv.w;
        }
        {
            float4 wv = *(const float4*)(wBase + lrow*I_SZ + kk0 + lchunk);
            Bs[lchunk+0][lrow] = wv.x;
            Bs[lchunk+1][lrow] = wv.y;
            Bs[lchunk+2][lrow] = wv.z;
            Bs[lchunk+3][lrow] = wv.w;
        }
        __syncthreads();
        #pragma unroll
        for (int kk = 0; kk < XB_BK; kk++) {
            float4 b4 = *(const float4*)&Bs[kk][tx*4];
            float4 a0 = *(const float4*)&As[kk][ty*8];
            float4 a1 = *(const float4*)&As[kk][ty*8+4];
            float a[8] = {a0.x,a0.y,a0.z,a0.w,a1.x,a1.y,a1.z,a1.w};
            float b[4] = {b4.x,b4.y,b4.z,b4.w};
            #pragma unroll
            for (int r = 0; r < 8; r++)
                #pragma unroll
                for (int c = 0; c < 4; c++)
                    acc[r][c] += a[r]*b[c];
        }
        __syncthreads();
    }
    float4 wb = *(const float4*)(Wb + g*H_SZ + n0 + tx*4);
    #pragma unroll
    for (int r = 0; r < 8; r++) {
        int b = ty*8 + r;           // batch index == row (BM==B)
        size_t oidx = (((size_t)t*B_SZ + b)*4 + g) * H_SZ + n0 + tx*4;
        float4 o = make_float4(acc[r][0]+wb.x, acc[r][1]+wb.y, acc[r][2]+wb.z, acc[r][3]+wb.w);
        *(float4*)(d_xpre + oidx) = o;
    }
}

// ---------------- persistent recurrent kernel ----------------
// 128 CTAs (8 b-groups x 16 k-groups), 256 threads, 1 grid barrier per step.
// smem (floats): U_s[4][256][16] | zh_s[4][256][17] | hm_s[4][256][17] |
//                s_s[2][4][16][16] | c_s[256] | ub_s[64]
#define RK_THREADS 256
#define RK_SMEM_FLOATS (4*256*16 + 4*256*17 + 4*256*17 + 2048 + 256 + 64)
#define RK_SMEM_BYTES (RK_SMEM_FLOATS*4)

__global__ __launch_bounds__(RK_THREADS, 1) void recurrent_kernel(
    const float* __restrict__ U, const float* __restrict__ Ub, float* __restrict__ out)
{
    extern __shared__ float sm[];
    float* U_s  = sm;
    float* zh_s = U_s  + 4*256*16;
    float* hm_s = zh_s + 4*256*17;
    float* s_s  = hm_s + 4*256*17;
    float* c_s  = s_s + 2048;
    float* ub_s = c_s + 256;

    int tid = threadIdx.x;
    int bi = blockIdx.x >> 4;  int b0 = bi * 16;
    int ki = blockIdx.x & 15;  int k0 = ki * 16;

    // one-time loads
    for (int e = tid; e < 16384; e += RK_THREADS) {       // U slice
        int g = e >> 12; int k = (e >> 8) & 15; int h = e & 255;
        U_s[(g*256 + h)*16 + k] = U[((size_t)(g*H_SZ + k0 + k))*H_SZ + h];
    }
    for (int e = tid; e < 16384; e += RK_THREADS) {       // zh slice
        int g = e >> 12; int b = (e >> 8) & 15; int h = e & 255;
        zh_s[(g*256 + h)*17 + b] = d_zh[((size_t)(g*B_SZ + b0 + b))*H_SZ + h];
    }
    if (tid < 64) ub_s[tid] = Ub[(tid >> 4)*H_SZ + k0 + (tid & 15)];
    c_s[tid] = 0.f;
    __syncthreads();

    int w = tid >> 5, lane = tid & 31;
    int g  = w & 3;
    int hh = (w >> 2) << 7;          // warp's h half: 0 or 128
    int kk = lane & 7;               // k-pair
    int bg = lane >> 3;              // 0..3 (4 b each)

    const float* Ug = U_s  + (g*256 + hh)*16 + 2*kk;
    const float* Hm = hm_s + (g*256 + hh)*17 + bg*4;
    int half = w >> 2;
    float* Sout = s_s + ((half*4 + g)*16 + bg*4)*16 + 2*kk;

    int eb = tid >> 4, ek = tid & 15;   // epilogue cell (b,k)

    float* hn     = out;
    float* ht_out = out + (size_t)T_STEPS*BH;
    float* ct_out = ht_out + BH;

    for (int t = 0; t < T_STEPS; t++) {
        // ---- build hm = h_prev * zh ----
        if (t == 0) {
            for (int p = tid; p < 4096; p += RK_THREADS) {
                int b = p >> 8, h = p & 255;
                #pragma unroll
                for (int gg = 0; gg < 4; gg++) hm_s[(gg*256 + h)*17 + b] = 0.f;
            }
        } else {
            const float* hprev = hn + (size_t)(t-1)*BH + (size_t)b0*H_SZ;
            for (int p = tid; p < 4096; p += RK_THREADS) {
                int b = p >> 8, h = p & 255;
                float hv = __ldcg(hprev + b*H_SZ + h);
                #pragma unroll
                for (int gg = 0; gg < 4; gg++)
                    hm_s[(gg*256 + h)*17 + b] = hv * zh_s[(gg*256 + h)*17 + b];
            }
        }
        __syncthreads();

        // ---- recurrent GEMM: 128-h half per warp ----
        float a00=0,a01=0,a10=0,a11=0,a20=0,a21=0,a30=0,a31=0;
        #pragma unroll 4
        for (int h = 0; h < 128; h++) {
            float2 u = *(const float2*)(Ug + h*16);
            float m0 = Hm[h*17 + 0];
            float m1 = Hm[h*17 + 1];
            float m2 = Hm[h*17 + 2];
            float m3 = Hm[h*17 + 3];
            a00 += m0*u.x; a01 += m0*u.y;
            a10 += m1*u.x; a11 += m1*u.y;
            a20 += m2*u.x; a21 += m2*u.y;
            a30 += m3*u.x; a31 += m3*u.y;
        }
        *(float2*)(Sout + 0*16) = make_float2(a00, a01);
        *(float2*)(Sout + 1*16) = make_float2(a10, a11);
        *(float2*)(Sout + 2*16) = make_float2(a20, a21);
        *(float2*)(Sout + 3*16) = make_float2(a30, a31);
        __syncthreads();

        // ---- epilogue: gates + state update ----
        {
            const float* xp = d_xpre + (((size_t)t*B_SZ + b0 + eb)*4)*H_SZ + k0 + ek;
            float s0 = s_s[(0*16+eb)*16+ek] + s_s[((4+0)*16+eb)*16+ek] + xp[0*H_SZ] + ub_s[ 0+ek];
            float s1 = s_s[(1*16+eb)*16+ek] + s_s[((4+1)*16+eb)*16+ek] + xp[1*H_SZ] + ub_s[16+ek];
            float s2 = s_s[(2*16+eb)*16+ek] + s_s[((4+2)*16+eb)*16+ek] + xp[2*H_SZ] + ub_s[32+ek];
            float s3 = s_s[(3*16+eb)*16+ek] + s_s[((4+3)*16+eb)*16+ek] + xp[3*H_SZ] + ub_s[48+ek];
            float iv = 1.f/(1.f+expf(-s0));
            float fv = 1.f/(1.f+expf(-s1));
            float ov = 1.f/(1.f+expf(-s2));
            float gv = tanhf(s3);
            float c  = fv * c_s[tid] + iv * gv;
            c_s[tid] = c;
            float hval = ov * tanhf(c);
            hn[(size_t)t*BH + (b0+eb)*H_SZ + k0+ek] = hval;
            if (t == T_STEPS-1) {
                ht_out[(b0+eb)*H_SZ + k0+ek] = hval;
                ct_out[(b0+eb)*H_SZ + k0+ek] = c;
            }
        }
        __threadfence();
        __syncthreads();

        // ---- grid barrier (all 128 CTAs co-resident: 1 CTA/SM, 128 <= 148) ----
        if (t < T_STEPS-1) {
            if (tid == 0) {
                atomicAdd(&g_bar, 1u);
                unsigned target = (unsigned)(t+1) * gridDim.x;
                while (*(volatile unsigned*)&g_bar < target) { }
            }
            __syncthreads();
        }
    }
}

// ---------------- launcher ----------------
extern "C" void kernel_launch(void* const* d_in, const int* in_sizes, int n_in,
                              void* d_out, int out_size) {
    const float* input = (const float*)d_in[0];
    const float* ux    = (const float*)d_in[1];
    const float* uh    = (const float*)d_in[2];
    const float* W     = (const float*)d_in[3];
    const float* Wb    = (const float*)d_in[4];
    const float* U     = (const float*)d_in[5];
    const float* Ub    = (const float*)d_in[6];
    float* out = (float*)d_out;

    (void)in_sizes; (void)n_in; (void)out_size;

    cudaFuncSetAttribute(recurrent_kernel,
                         cudaFuncAttributeMaxDynamicSharedMemorySize, RK_SMEM_BYTES);

    reset_kernel<<<1, 1>>>();
    mask_kernel<<<512, 256>>>(ux, uh);
    xpre_kernel<<<dim3(T_STEPS, I_SZ/XB_BN, 4), 256>>>(input, W, Wb);
    recurrent_kernel<<<128, RK_THREADS, RK_SMEM_BYTES>>>(U, Ub, out);
}

// round 3
// speedup vs baseline: 1.1373x; 1.1373x over previous
#include <cuda_runtime.h>
#include <cstdint>

#define T_STEPS 512
#define B_SZ 128
#define I_SZ 256
#define H_SZ 256
#define BH (B_SZ*H_SZ)

typedef unsigned long long ull;

// ---------------- f32x2 helpers (sm_100+/sm_103a packed fp32) ----------------
__device__ __forceinline__ ull pack2(float x, float y) {
    ull r; asm("mov.b64 %0, {%1,%2};" : "=l"(r) : "f"(x), "f"(y)); return r;
}
__device__ __forceinline__ void unpack2(float& x, float& y, ull v) {
    asm("mov.b64 {%0,%1}, %2;" : "=f"(x), "=f"(y) : "l"(v));
}
__device__ __forceinline__ void fma2(ull& d, ull a, ull b) {
    asm("fma.rn.f32x2 %0, %1, %2, %0;" : "+l"(d) : "l"(a), "l"(b));
}
__device__ __forceinline__ ull mul2(ull a, ull b) {
    ull r; asm("mul.rn.f32x2 %0, %1, %2;" : "=l"(r) : "l"(a), "l"(b)); return r;
}

// ---------------- device scratch ----------------
__device__ float d_zx[4*B_SZ*I_SZ];                       // (4,B,I)
__device__ float d_zh[4*B_SZ*H_SZ];                       // (4,B,H)
__device__ float d_xpre[(size_t)T_STEPS*B_SZ*4*H_SZ];     // (T,B,4,H) 256MB
__device__ unsigned g_bars[8];

__global__ void reset_kernel() { if (threadIdx.x < 8) g_bars[threadIdx.x] = 0u; }

// ---------------- masks ----------------
__device__ __forceinline__ float concrete_mask(float u) {
    const float EPSC = 1e-7f;
    float logit_p = logf(0.25f + EPSC) - logf(0.75f + EPSC);
    float lu = logf(u + EPSC) - logf(1.0f - u + EPSC);
    float x = (logit_p + lu) / 0.1f;
    float s = 1.0f / (1.0f + expf(-x));
    return (1.0f - s) / 0.75f;
}

__global__ void mask_kernel(const float* __restrict__ ux, const float* __restrict__ uh) {
    int i = blockIdx.x * blockDim.x + threadIdx.x;
    if (i < 4*B_SZ*I_SZ) {
        d_zx[i] = concrete_mask(ux[i]);
        d_zh[i] = concrete_mask(uh[i]);
    }
}

// ---------------- x_pre GEMM (FFMA2) ----------------
// x_pre[t,b,g,h] = sum_i input[t,b,i]*zx[g,b,i]*W[g,h,i] + Wb[g,h]
#define XB_BM 128
#define XB_BN 64
#define XB_BK 16

__global__ __launch_bounds__(256) void xpre_kernel(
    const float* __restrict__ input, const float* __restrict__ W, const float* __restrict__ Wb)
{
    __shared__ float As[XB_BK][XB_BM+4];
    __shared__ float Bs[XB_BK][XB_BN+4];
    int g  = blockIdx.z;
    int t  = blockIdx.x;            // m0 = t*128 (row == batch)
    int n0 = blockIdx.y * XB_BN;
    int tid = threadIdx.x;
    int tx = tid & 15, ty = tid >> 4;

    // acc[rpair][c]: packed rows (ty*8+2p, ty*8+2p+1), column n0+tx*4+c
    ull acc[4][4];
    #pragma unroll
    for (int p = 0; p < 4; p++)
        #pragma unroll
        for (int c = 0; c < 4; c++) acc[p][c] = 0ull;

    const float* inpBase = input + (size_t)t * (B_SZ*I_SZ);
    const float* zxBase  = d_zx + g * (B_SZ*I_SZ);
    const float* wBase   = W + (size_t)g * (H_SZ*I_SZ) + (size_t)n0 * I_SZ;

    int lrow   = tid >> 2;          // 0..63
    int lchunk = (tid & 3) * 4;     // 0,4,8,12

    for (int kk0 = 0; kk0 < I_SZ; kk0 += XB_BK) {
        #pragma unroll
        for (int it = 0; it < 2; it++) {
            int row = lrow + it*64;
            float4 av = *(const float4*)(inpBase + row*I_SZ + kk0 + lchunk);
            float4 zv = *(const float4*)(zxBase  + row*I_SZ + kk0 + lchunk);
            As[lchunk+0][row] = av.x*zv.x;
            As[lchunk+1][row] = av.y*zv.y;
            As[lchunk+2][row] = av.z*zv.z;
            As[lchunk+3][row] = av.w*zv.w;
        }
        {
            float4 wv = *(const float4*)(wBase + lrow*I_SZ + kk0 + lchunk);
            Bs[lchunk+0][lrow] = wv.x;
            Bs[lchunk+1][lrow] = wv.y;
            Bs[lchunk+2][lrow] = wv.z;
            Bs[lchunk+3][lrow] = wv.w;
        }
        __syncthreads();
        #pragma unroll
        for (int kk = 0; kk < XB_BK; kk++) {
            float4 b4 = *(const float4*)&Bs[kk][tx*4];
            ulonglong2 a01 = *(const ulonglong2*)&As[kk][ty*8];
            ulonglong2 a23 = *(const ulonglong2*)&As[kk][ty*8+4];
            ull ap[4] = {a01.x, a01.y, a23.x, a23.y};
            ull bb[4] = {pack2(b4.x,b4.x), pack2(b4.y,b4.y),
                         pack2(b4.z,b4.z), pack2(b4.w,b4.w)};
            #pragma unroll
            for (int p = 0; p < 4; p++)
                #pragma unroll
                for (int c = 0; c < 4; c++)
                    fma2(acc[p][c], ap[p], bb[c]);
        }
        __syncthreads();
    }
    float4 wb = *(const float4*)(Wb + g*H_SZ + n0 + tx*4);
    #pragma unroll
    for (int p = 0; p < 4; p++) {
        float lo[4], hi[4];
        #pragma unroll
        for (int c = 0; c < 4; c++) unpack2(lo[c], hi[c], acc[p][c]);
        int b0r = ty*8 + 2*p;
        size_t o0 = (((size_t)t*B_SZ + b0r)*4 + g) * H_SZ + n0 + tx*4;
        size_t o1 = (((size_t)t*B_SZ + b0r+1)*4 + g) * H_SZ + n0 + tx*4;
        *(float4*)(d_xpre + o0) = make_float4(lo[0]+wb.x, lo[1]+wb.y, lo[2]+wb.z, lo[3]+wb.w);
        *(float4*)(d_xpre + o1) = make_float4(hi[0]+wb.x, hi[1]+wb.y, hi[2]+wb.z, hi[3]+wb.w);
    }
}

// ---------------- persistent recurrent kernel ----------------
// 128 CTAs (8 b-groups x 16 k-groups), 256 threads.
// smem floats: U_s[4][256][16] | zh_s[4][256][18] | hm_s[4][256][18] |
//              s_s[2][4][16][18] | c_s[256] | ub_s[64]
#define RK_THREADS 256
#define RK_SMEM_FLOATS (4*256*16 + 4*256*18 + 4*256*18 + 2*4*16*18 + 256 + 64)
#define RK_SMEM_BYTES (RK_SMEM_FLOATS*4)

__global__ __launch_bounds__(RK_THREADS, 1) void recurrent_kernel(
    const float* __restrict__ U, const float* __restrict__ Ub, float* __restrict__ out)
{
    extern __shared__ float sm[];
    float* U_s  = sm;                       // 16384
    float* zh_s = U_s  + 4*256*16;          // 18432
    float* hm_s = zh_s + 4*256*18;          // 18432
    float* s_s  = hm_s + 4*256*18;          // 2304
    float* c_s  = s_s + 2*4*16*18;          // 256
    float* ub_s = c_s + 256;                // 64

    int tid = threadIdx.x;
    int bi = blockIdx.x >> 4;  int b0 = bi * 16;
    int ki = blockIdx.x & 15;  int k0 = ki * 16;

    // one-time loads
    for (int e = tid; e < 16384; e += RK_THREADS) {       // U slice: U_s[(g,h)][k] = U[g,k0+k,h]
        int g = e >> 12; int k = (e >> 8) & 15; int h = e & 255;
        U_s[(g*256 + h)*16 + k] = U[((size_t)(g*H_SZ + k0 + k))*H_SZ + h];
    }
    for (int e = tid; e < 16384; e += RK_THREADS) {       // zh slice
        int g = e >> 12; int b = (e >> 8) & 15; int h = e & 255;
        zh_s[(g*256 + h)*18 + b] = d_zh[((size_t)(g*B_SZ + b0 + b))*H_SZ + h];
    }
    if (tid < 64) ub_s[tid] = Ub[(tid >> 4)*H_SZ + k0 + (tid & 15)];
    c_s[tid] = 0.f;
    __syncthreads();

    // GEMM warp layout: w = (half, g); lane = (bg 0..7, kq 0..3)
    int w = tid >> 5, lane = tid & 31;
    int g    = w & 3;
    int half = w >> 2;
    int hbase = half << 7;
    int kq = lane & 3;
    int bg = lane >> 2;
    const float* Ug = U_s  + (g*256 + hbase)*16 + kq*4;
    const float* Hm = hm_s + (g*256 + hbase)*18 + bg*2;
    float* Sout = s_s + ((half*4 + g)*16 + bg*2)*18 + kq*4;

    int eb = tid >> 4, ek = tid & 15;   // epilogue cell (b,k)

    float* hn     = out;
    float* ht_out = out + (size_t)T_STEPS*BH;
    float* ct_out = ht_out + BH;

    unsigned* mybar = &g_bars[bi];

    for (int t = 0; t < T_STEPS; t++) {
        // ---- prefetch x_pre gate values for this step (consumed in epilogue) ----
        const float* xpp = d_xpre + (((size_t)t*B_SZ + b0 + eb)*4)*H_SZ + k0 + ek;
        float xp0 = __ldcs(xpp);
        float xp1 = __ldcs(xpp + H_SZ);
        float xp2 = __ldcs(xpp + 2*H_SZ);
        float xp3 = __ldcs(xpp + 3*H_SZ);

        // ---- build hm = h_prev * zh (packed over b-pairs) ----
        if (t == 0) {
            for (int e = tid; e < 4*256*18; e += RK_THREADS) hm_s[e] = 0.f;
        } else {
            const float* hprev = hn + (size_t)(t-1)*BH + (size_t)b0*H_SZ;
            int h = tid;
            float hv0[8], hv1[8];
            #pragma unroll
            for (int b2 = 0; b2 < 8; b2++) {
                hv0[b2] = __ldcg(hprev + (2*b2)*H_SZ + h);
                hv1[b2] = __ldcg(hprev + (2*b2+1)*H_SZ + h);
            }
            #pragma unroll
            for (int b2 = 0; b2 < 8; b2++) {
                ull hp = pack2(hv0[b2], hv1[b2]);
                #pragma unroll
                for (int gg = 0; gg < 4; gg++) {
                    ull z = *(const ull*)&zh_s[(gg*256+h)*18 + 2*b2];
                    *(ull*)&hm_s[(gg*256+h)*18 + 2*b2] = mul2(hp, z);
                }
            }
        }
        __syncthreads();

        // ---- recurrent GEMM: per warp 16k x 16b over 128 h, FFMA2 ----
        {
            ull a0 = 0ull, a1 = 0ull, a2 = 0ull, a3 = 0ull;
            #pragma unroll 4
            for (int h = 0; h < 128; h++) {
                ulonglong2 u = *(const ulonglong2*)(Ug + h*16);
                float2 m = *(const float2*)(Hm + h*18);
                ull m0 = pack2(m.x, m.x);
                ull m1 = pack2(m.y, m.y);
                fma2(a0, u.x, m0);
                fma2(a1, u.y, m0);
                fma2(a2, u.x, m1);
                fma2(a3, u.y, m1);
            }
            *(ull*)(Sout + 0)  = a0;
            *(ull*)(Sout + 2)  = a1;
            *(ull*)(Sout + 18) = a2;
            *(ull*)(Sout + 20) = a3;
        }
        __syncthreads();

        // ---- epilogue: gates + state update ----
        {
            float s0 = s_s[((0)*16+eb)*18+ek] + s_s[((4+0)*16+eb)*18+ek] + xp0 + ub_s[ 0+ek];
            float s1 = s_s[((1)*16+eb)*18+ek] + s_s[((4+1)*16+eb)*18+ek] + xp1 + ub_s[16+ek];
            float s2 = s_s[((2)*16+eb)*18+ek] + s_s[((4+2)*16+eb)*18+ek] + xp2 + ub_s[32+ek];
            float s3 = s_s[((3)*16+eb)*18+ek] + s_s[((4+3)*16+eb)*18+ek] + xp3 + ub_s[48+ek];
            float iv = __fdividef(1.f, 1.f + __expf(-s0));
            float fv = __fdividef(1.f, 1.f + __expf(-s1));
            float ov = __fdividef(1.f, 1.f + __expf(-s2));
            float gv = __fdividef(2.f, 1.f + __expf(-2.f*s3)) - 1.f;
            float c  = fv * c_s[tid] + iv * gv;
            c_s[tid] = c;
            float th = __fdividef(2.f, 1.f + __expf(-2.f*c)) - 1.f;
            float hval = ov * th;
            hn[(size_t)t*BH + (b0+eb)*H_SZ + k0+ek] = hval;
            if (t == T_STEPS-1) {
                ht_out[(b0+eb)*H_SZ + k0+ek] = hval;
                ct_out[(b0+eb)*H_SZ + k0+ek] = c;
            }
        }
        __threadfence();
        __syncthreads();

        // ---- per-b-group barrier: only the 16 CTAs sharing bi must sync ----
        if (t < T_STEPS-1) {
            if (tid == 0) {
                atomicAdd(mybar, 1u);
                unsigned target = (unsigned)(t+1) * 16u;
                while (*(volatile unsigned*)mybar < target) { }
            }
            __syncthreads();
        }
    }
}

// ---------------- launcher ----------------
extern "C" void kernel_launch(void* const* d_in, const int* in_sizes, int n_in,
                              void* d_out, int out_size) {
    const float* input = (const float*)d_in[0];
    const float* ux    = (const float*)d_in[1];
    const float* uh    = (const float*)d_in[2];
    const float* W     = (const float*)d_in[3];
    const float* Wb    = (const float*)d_in[4];
    const float* U     = (const float*)d_in[5];
    const float* Ub    = (const float*)d_in[6];
    float* out = (float*)d_out;

    (void)in_sizes; (void)n_in; (void)out_size;

    cudaFuncSetAttribute(recurrent_kernel,
                         cudaFuncAttributeMaxDynamicSharedMemorySize, RK_SMEM_BYTES);

    reset_kernel<<<1, 32>>>();
    mask_kernel<<<512, 256>>>(ux, uh);
    xpre_kernel<<<dim3(T_STEPS, I_SZ/XB_BN, 4), 256>>>(input, W, Wb);
    recurrent_kernel<<<128, RK_THREADS, RK_SMEM_BYTES>>>(U, Ub, out);
}